// round 1
// baseline (speedup 1.0000x reference)
#include <cuda_runtime.h>

#define POOL 14
#define H 128
#define W 128
#define C 1024
#define R 256

// One CTA per output pixel (roi, py, px). 256 threads, each handles one
// float4 (4 channels) of the 1024-channel vector. All 4 bilinear corner
// reads are contiguous 4KB segments -> fully coalesced.
__global__ __launch_bounds__(256) void roi_resize_kernel(
    const float4* __restrict__ img,   // [H, W, C/4] float4
    const float*  __restrict__ rois,  // [R, 4]
    float4*       __restrict__ out)   // [R, POOL, POOL, C/4]
{
    const int p  = blockIdx.x;          // 0..195  (py*14+px)
    const int r  = blockIdx.y;          // 0..255
    const int py = p / POOL;
    const int px = p % POOL;
    const int c4 = threadIdx.x;         // 0..255 (float4 channel group)

    // ROI box (values are nonnegative integers stored as float)
    const int x1 = (int)rois[r * 4 + 0];
    const int y1 = (int)rois[r * 4 + 1];
    const int x2 = (int)rois[r * 4 + 2];
    const int y2 = (int)rois[r * 4 + 3];

    const float hh = (float)(y2 - y1);
    const float ww = (float)(x2 - x1);

    // src coords: i * (h / pool), floor, frac  (matches reference exactly)
    const float src_y = (float)py * (hh * (1.0f / POOL));
    const float src_x = (float)px * (ww * (1.0f / POOL));
    const int y0 = (int)floorf(src_y);
    const int x0 = (int)floorf(src_x);
    const float fy = src_y - (float)y0;
    const float fx = src_x - (float)x0;

    const int y1i = min(y0 + 1, (y2 - y1) - 1);
    const int x1i = min(x0 + 1, (x2 - x1) - 1);

    const int ay0 = min(max(y1 + y0, 0), H - 1);
    const int ay1 = min(max(y1 + y1i, 0), H - 1);
    const int ax0 = min(max(x1 + x0, 0), W - 1);
    const int ax1 = min(max(x1 + x1i, 0), W - 1);

    const int C4 = C / 4;
    const float4 v00 = img[(ay0 * W + ax0) * C4 + c4];
    const float4 v01 = img[(ay0 * W + ax1) * C4 + c4];
    const float4 v10 = img[(ay1 * W + ax0) * C4 + c4];
    const float4 v11 = img[(ay1 * W + ax1) * C4 + c4];

    float4 o;
    {
        float top = v00.x + (v01.x - v00.x) * fx;
        float bot = v10.x + (v11.x - v10.x) * fx;
        o.x = top + (bot - top) * fy;
    }
    {
        float top = v00.y + (v01.y - v00.y) * fx;
        float bot = v10.y + (v11.y - v10.y) * fx;
        o.y = top + (bot - top) * fy;
    }
    {
        float top = v00.z + (v01.z - v00.z) * fx;
        float bot = v10.z + (v11.z - v10.z) * fx;
        o.z = top + (bot - top) * fy;
    }
    {
        float top = v00.w + (v01.w - v00.w) * fx;
        float bot = v10.w + (v11.w - v10.w) * fx;
        o.w = top + (bot - top) * fy;
    }

    out[(r * (POOL * POOL) + p) * C4 + c4] = o;
}

extern "C" void kernel_launch(void* const* d_in, const int* in_sizes, int n_in,
                              void* d_out, int out_size) {
    const float4* img  = (const float4*)d_in[0];
    const float*  rois = (const float*)d_in[1];
    float4*       out  = (float4*)d_out;

    dim3 grid(POOL * POOL, R);
    roi_resize_kernel<<<grid, 256>>>(img, rois, out);
}

// round 2
// speedup vs baseline: 1.1580x; 1.1580x over previous
#include <cuda_runtime.h>

#define POOL 14
#define H 128
#define W 128
#define C 1024
#define R 256
#define C4 (C / 4)

// One CTA per (roi, py) output row: 14 px * 1024 ch.
// Threads 0..13 precompute x-side gather indices/weights into shared once;
// y-side scalars computed once per CTA. Loop body = 4 coalesced LDG.128 +
// lerp + 1 streaming STG.128 per px.
__global__ __launch_bounds__(256) void roi_resize_kernel(
    const float4* __restrict__ img,   // [H, W, C4]
    const float*  __restrict__ rois,  // [R, 4]
    float4*       __restrict__ out)   // [R, POOL, POOL, C4]
{
    const int py = blockIdx.x;          // 0..13
    const int r  = blockIdx.y;          // 0..255
    const int c4 = threadIdx.x;         // 0..255

    __shared__ int   s_ax0[POOL];
    __shared__ int   s_ax1[POOL];
    __shared__ float s_fx [POOL];

    // ROI box (nonnegative integers stored as float)
    const int x1 = (int)rois[r * 4 + 0];
    const int y1 = (int)rois[r * 4 + 1];
    const int x2 = (int)rois[r * 4 + 2];
    const int y2 = (int)rois[r * 4 + 3];

    // x-side: 14 entries, computed by threads 0..13
    if (threadIdx.x < POOL) {
        const float ww = (float)(x2 - x1);
        const float src_x = (float)threadIdx.x * (ww * (1.0f / POOL));
        const int   x0 = (int)floorf(src_x);
        const int   x1i = min(x0 + 1, (x2 - x1) - 1);
        s_fx [threadIdx.x] = src_x - (float)x0;
        s_ax0[threadIdx.x] = min(max(x1 + x0, 0), W - 1);
        s_ax1[threadIdx.x] = min(max(x1 + x1i, 0), W - 1);
    }

    // y-side: scalars, once per CTA (replicated per thread, cheap)
    const float hh = (float)(y2 - y1);
    const float src_y = (float)py * (hh * (1.0f / POOL));
    const int   y0 = (int)floorf(src_y);
    const float fy = src_y - (float)y0;
    const int   y1i = min(y0 + 1, (y2 - y1) - 1);
    const int   ay0 = min(max(y1 + y0, 0), H - 1);
    const int   ay1 = min(max(y1 + y1i, 0), H - 1);

    __syncthreads();

    const float4* __restrict__ row0 = img + (size_t)(ay0 * W) * C4 + c4;
    const float4* __restrict__ row1 = img + (size_t)(ay1 * W) * C4 + c4;
    float4* __restrict__ orow = out + ((size_t)(r * POOL + py) * POOL) * C4 + c4;

    #pragma unroll
    for (int px = 0; px < POOL; px++) {
        const int   ax0 = s_ax0[px];
        const int   ax1 = s_ax1[px];
        const float fx  = s_fx[px];

        const float4 v00 = row0[ax0 * C4];
        const float4 v01 = row0[ax1 * C4];
        const float4 v10 = row1[ax0 * C4];
        const float4 v11 = row1[ax1 * C4];

        float4 o;
        {
            float top = v00.x + (v01.x - v00.x) * fx;
            float bot = v10.x + (v11.x - v10.x) * fx;
            o.x = top + (bot - top) * fy;
        }
        {
            float top = v00.y + (v01.y - v00.y) * fx;
            float bot = v10.y + (v11.y - v10.y) * fx;
            o.y = top + (bot - top) * fy;
        }
        {
            float top = v00.z + (v01.z - v00.z) * fx;
            float bot = v10.z + (v11.z - v10.z) * fx;
            o.z = top + (bot - top) * fy;
        }
        {
            float top = v00.w + (v01.w - v00.w) * fx;
            float bot = v10.w + (v11.w - v10.w) * fx;
            o.w = top + (bot - top) * fy;
        }

        __stcs(&orow[(size_t)px * C4], o);   // streaming: don't pollute L2
    }
}

extern "C" void kernel_launch(void* const* d_in, const int* in_sizes, int n_in,
                              void* d_out, int out_size) {
    const float4* img  = (const float4*)d_in[0];
    const float*  rois = (const float*)d_in[1];
    float4*       out  = (float4*)d_out;

    dim3 grid(POOL, R);
    roi_resize_kernel<<<grid, 256>>>(img, rois, out);
}